// round 2
// baseline (speedup 1.0000x reference)
#include <cuda_runtime.h>
#include <math.h>
#include <stdint.h>

#define NN 50000
#define NE 600000
#define DD 128
#define EPS_V 1e-5f
#define AVG_D_LOG 1.6094379124341003f

typedef unsigned long long u64;

// ---------------- scratch ----------------
__device__ float g_PQ[(size_t)NN * 256];       // [P | Q+b_pre]
__device__ float g_agg[(size_t)NN * 512];      // [mean | max | min | std]
__device__ float g_G[(size_t)NN * 384];        // agg @ Wcat
__device__ float g_hp[(size_t)NN * 128];
__device__ float g_s1[NN];
__device__ float g_s2[NN];
__device__ int   g_count[NN];
__device__ int   g_offsets[NN + 1];
__device__ int   g_cursor[NN];
__device__ int   g_sorted_src[NE];
__device__ float g_B1[128 * 256];
__device__ float g_Wcat[512 * 384];
__device__ float g_bias1[256];
__device__ int   g_blocksums[64];
__device__ int   g_blockoff[64];
__device__ int   g_is64;

// ---------------- index dtype detection ----------------
__global__ void detect_kernel(const void* edst) {
    const int* v = (const int*)edst;
    g_is64 = (v[1] == 0 && v[3] == 0) ? 1 : 0;
}

__device__ __forceinline__ int edge_index(const void* p, int i) {
    if (g_is64) return (int)(((const long long*)p)[i]);
    return ((const int*)p)[i];
}

// ---------------- prep: zero counters, pack B1 / Wcat / bias1 ----------------
__global__ void prep_kernel(const float* __restrict__ W_pre,
                            const float* __restrict__ b_pre,
                            const float* __restrict__ W_post) {
    int idx = blockIdx.x * blockDim.x + threadIdx.x;
    if (idx < NN) g_count[idx] = 0;
    if (idx < 256) g_bias1[idx] = (idx < 128) ? 0.f : b_pre[idx - 128];
    if (idx < 128 * 256) {
        int k = idx >> 8;
        int c = idx & 255;
        g_B1[idx] = (c < 128) ? W_pre[k * 128 + c] : W_pre[(128 + k) * 128 + (c - 128)];
    }
    if (idx < 512 * 384) {
        int k = idx / 384;
        int j = idx % 384;
        int grp = j >> 7;
        int jj = j & 127;
        g_Wcat[idx] = W_post[(size_t)(128 + grp * 512 + k) * 128 + jj];
    }
}

// ---------------- histogram of edge_dst ----------------
__global__ void hist_kernel(const void* __restrict__ edst) {
    int e = blockIdx.x * blockDim.x + threadIdx.x;
    if (e < NE) {
        int d = edge_index(edst, e);
        atomicAdd(&g_count[d], 1);
    }
}

// ---------------- parallel 3-phase exclusive scan ----------------
#define SCAN_BLOCKS ((NN + 1023) / 1024)   // 49

__global__ void __launch_bounds__(1024) scanA_kernel() {
    __shared__ int sdata[1024];
    int tid = threadIdx.x;
    int i = blockIdx.x * 1024 + tid;
    int v = (i < NN) ? g_count[i] : 0;
    sdata[tid] = v;
    __syncthreads();
    #pragma unroll
    for (int off = 1; off < 1024; off <<= 1) {
        int t = (tid >= off) ? sdata[tid - off] : 0;
        __syncthreads();
        sdata[tid] += t;
        __syncthreads();
    }
    if (i < NN) g_offsets[i] = sdata[tid] - v;   // local exclusive
    if (tid == 1023) g_blocksums[blockIdx.x] = sdata[1023];
}

__global__ void scanB_kernel() {
    if (threadIdx.x == 0) {
        int run = 0;
        for (int b = 0; b < SCAN_BLOCKS; b++) {
            g_blockoff[b] = run;
            run += g_blocksums[b];
        }
    }
}

__global__ void __launch_bounds__(1024) scanC_kernel() {
    int tid = threadIdx.x;
    int i = blockIdx.x * 1024 + tid;
    if (i < NN) {
        int o = g_offsets[i] + g_blockoff[blockIdx.x];
        g_offsets[i] = o;
        g_cursor[i] = o;
    }
    if (i == 0) g_offsets[NN] = NE;
}

// ---------------- scatter edges into CSR order ----------------
__global__ void scatter_kernel(const void* __restrict__ esrc, const void* __restrict__ edst) {
    int e = blockIdx.x * blockDim.x + threadIdx.x;
    if (e < NE) {
        int d = edge_index(edst, e);
        int s = edge_index(esrc, e);
        int pos = atomicAdd(&g_cursor[d], 1);
        g_sorted_src[pos] = s;
    }
}

// ---------------- f32x2 packed SGEMM, 128x128 tile, 8x8 per thread ----------------
// mode 0: C = acc (+bias)
// mode 1: C = relu(acc + bias + G0 + s1*G1 + s2*G2)   (N must be 128)
// mode 2: C = resid + leaky_relu(acc + bias)          (N must be 128)
__global__ void __launch_bounds__(256) sgemm_kernel(
    const float* __restrict__ A, const float* __restrict__ B, float* __restrict__ C,
    int M, int N, int K, int mode,
    const float* __restrict__ bias,
    const float* __restrict__ Gx,
    const float* __restrict__ s1p, const float* __restrict__ s2p,
    const float* __restrict__ resid)
{
    __shared__ float2 As2[16][128];   // duplicated pairs {v,v}
    __shared__ float  Bs[16][128];
    int tid = threadIdx.x;
    int blockRow = blockIdx.x * 128;
    int blockCol = blockIdx.y * 128;
    int tr = (tid / 16) * 8;
    int tc = (tid % 16) * 8;

    u64 acc2[8][4];
    #pragma unroll
    for (int i = 0; i < 8; i++)
        #pragma unroll
        for (int j = 0; j < 4; j++) acc2[i][j] = 0ull;

    int aRow0 = tid >> 2;         // 0..63
    int aCol  = (tid & 3) * 4;    // 0,4,8,12
    int bRow0 = tid >> 5;         // 0..7
    int bCol  = (tid & 31) * 4;   // 0..124

    for (int k0 = 0; k0 < K; k0 += 16) {
        #pragma unroll
        for (int half = 0; half < 2; half++) {
            int r = aRow0 + half * 64;
            int gr = blockRow + r;
            if (gr > M - 1) gr = M - 1;
            float4 v = *reinterpret_cast<const float4*>(&A[(size_t)gr * K + k0 + aCol]);
            As2[aCol + 0][r] = make_float2(v.x, v.x);
            As2[aCol + 1][r] = make_float2(v.y, v.y);
            As2[aCol + 2][r] = make_float2(v.z, v.z);
            As2[aCol + 3][r] = make_float2(v.w, v.w);
        }
        #pragma unroll
        for (int half = 0; half < 2; half++) {
            int r = bRow0 + half * 8;
            float4 v = *reinterpret_cast<const float4*>(&B[(size_t)(k0 + r) * N + blockCol + bCol]);
            *reinterpret_cast<float4*>(&Bs[r][bCol]) = v;
        }
        __syncthreads();
        #pragma unroll
        for (int k = 0; k < 16; k++) {
            ulonglong2 a01 = *reinterpret_cast<ulonglong2*>(&As2[k][tr]);
            ulonglong2 a23 = *reinterpret_cast<ulonglong2*>(&As2[k][tr + 2]);
            ulonglong2 a45 = *reinterpret_cast<ulonglong2*>(&As2[k][tr + 4]);
            ulonglong2 a67 = *reinterpret_cast<ulonglong2*>(&As2[k][tr + 6]);
            ulonglong2 b01 = *reinterpret_cast<ulonglong2*>(&Bs[k][tc]);
            ulonglong2 b23 = *reinterpret_cast<ulonglong2*>(&Bs[k][tc + 4]);
            u64 a[8] = {a01.x, a01.y, a23.x, a23.y, a45.x, a45.y, a67.x, a67.y};
            u64 b[4] = {b01.x, b01.y, b23.x, b23.y};
            #pragma unroll
            for (int i = 0; i < 8; i++)
                #pragma unroll
                for (int j = 0; j < 4; j++)
                    asm("fma.rn.f32x2 %0, %1, %2, %0;"
                        : "+l"(acc2[i][j]) : "l"(a[i]), "l"(b[j]));
        }
        __syncthreads();
    }

    #pragma unroll
    for (int i = 0; i < 8; i++) {
        int row = blockRow + tr + i;
        if (row >= M) break;
        float s1v = 0.f, s2v = 0.f;
        if (mode == 1) { s1v = s1p[row]; s2v = s2p[row]; }
        #pragma unroll
        for (int p = 0; p < 4; p++) {
            u64 u = acc2[i][p];
            float vlo = __uint_as_float((unsigned)(u & 0xffffffffull));
            float vhi = __uint_as_float((unsigned)(u >> 32));
            #pragma unroll
            for (int q = 0; q < 2; q++) {
                int col = blockCol + tc + 2 * p + q;
                float v = q ? vhi : vlo;
                if (bias) v += bias[col];
                if (mode == 1) {
                    const float* g = &Gx[(size_t)row * 384];
                    v += g[col] + s1v * g[col + 128] + s2v * g[col + 256];
                    v = fmaxf(v, 0.f);
                } else if (mode == 2) {
                    v = (v > 0.f) ? v : 0.01f * v;
                    v += resid[(size_t)row * 128 + col];
                }
                C[(size_t)row * N + col] = v;
            }
        }
    }
}

// ---------------- per-node multi-aggregator ----------------
__global__ void __launch_bounds__(128) aggregate_kernel() {
    int n = blockIdx.x;
    int d = threadIdx.x;
    int start = g_offsets[n];
    int end = g_offsets[n + 1];
    float qd = g_PQ[(size_t)n * 256 + 128 + d];
    float s = 0.f, sq = 0.f;
    float mx = -3.4e38f, mn = 3.4e38f;
    for (int i = start; i < end; i++) {
        int src = g_sorted_src[i];
        float v = g_PQ[(size_t)src * 256 + d] + qd;
        v = fmaxf(v, 0.f);
        s += v;
        sq += v * v;
        mx = fmaxf(mx, v);
        mn = fminf(mn, v);
    }
    float degf = (float)(end - start);
    float inv = 1.f / degf;
    float mean = s * inv;
    float msq = sq * inv;
    float var = fmaxf(msq - mean * mean, 0.f);
    float sd = sqrtf(var + EPS_V);
    size_t base = (size_t)n * 512;
    g_agg[base + d] = mean;
    g_agg[base + 128 + d] = mx;
    g_agg[base + 256 + d] = mn;
    g_agg[base + 384 + d] = sd;
    if (d == 0) {
        float ld = logf(degf + 1.f);
        g_s1[n] = ld / AVG_D_LOG;
        g_s2[n] = AVG_D_LOG / ld;
    }
}

// ---------------- launch ----------------
extern "C" void kernel_launch(void* const* d_in, const int* in_sizes, int n_in,
                              void* d_out, int out_size) {
    const float* h      = (const float*)d_in[0];
    const void*  esrc   = d_in[1];
    const void*  edst   = d_in[2];
    const float* W_pre  = (const float*)d_in[3];
    const float* b_pre  = (const float*)d_in[4];
    const float* W_post = (const float*)d_in[5];
    const float* b_post = (const float*)d_in[6];
    const float* W_mix  = (const float*)d_in[7];
    const float* b_mix  = (const float*)d_in[8];
    float* out = (float*)d_out;

    float *g_PQ_p, *g_agg_p, *g_G_p, *g_hp_p, *g_s1_p, *g_s2_p, *g_B1_p, *g_Wcat_p, *g_bias1_p;
    cudaGetSymbolAddress((void**)&g_PQ_p, g_PQ);
    cudaGetSymbolAddress((void**)&g_agg_p, g_agg);
    cudaGetSymbolAddress((void**)&g_G_p, g_G);
    cudaGetSymbolAddress((void**)&g_hp_p, g_hp);
    cudaGetSymbolAddress((void**)&g_s1_p, g_s1);
    cudaGetSymbolAddress((void**)&g_s2_p, g_s2);
    cudaGetSymbolAddress((void**)&g_B1_p, g_B1);
    cudaGetSymbolAddress((void**)&g_Wcat_p, g_Wcat);
    cudaGetSymbolAddress((void**)&g_bias1_p, g_bias1);

    detect_kernel<<<1, 1>>>(edst);
    prep_kernel<<<768, 256>>>(W_pre, b_pre, W_post);
    hist_kernel<<<(NE + 255) / 256, 256>>>(edst);
    scanA_kernel<<<SCAN_BLOCKS, 1024>>>();
    scanB_kernel<<<1, 32>>>();
    scanC_kernel<<<SCAN_BLOCKS, 1024>>>();
    scatter_kernel<<<(NE + 255) / 256, 256>>>(esrc, edst);

    // GEMM1: PQ = h @ B1 (+ bias1)   M=50000, N=256, K=128
    {
        dim3 grid((NN + 127) / 128, 2);
        sgemm_kernel<<<grid, 256>>>(h, g_B1_p, g_PQ_p, NN, 256, 128, 0,
                                    g_bias1_p, nullptr, nullptr, nullptr, nullptr);
    }

    aggregate_kernel<<<NN, 128>>>();

    // GEMM2: G = agg @ Wcat   M=50000, N=384, K=512
    {
        dim3 grid((NN + 127) / 128, 3);
        sgemm_kernel<<<grid, 256>>>(g_agg_p, g_Wcat_p, g_G_p, NN, 384, 512, 0,
                                    nullptr, nullptr, nullptr, nullptr, nullptr);
    }

    // GEMM3: hp = relu(h @ W_post[0:128] + comb(G, s1, s2) + b_post)
    {
        dim3 grid((NN + 127) / 128, 1);
        sgemm_kernel<<<grid, 256>>>(h, W_post, g_hp_p, NN, 128, 128, 1,
                                    b_post, g_G_p, g_s1_p, g_s2_p, nullptr);
    }

    // GEMM4: out = h + leaky_relu(hp @ W_mix + b_mix)
    {
        dim3 grid((NN + 127) / 128, 1);
        sgemm_kernel<<<grid, 256>>>(g_hp_p, W_mix, out, NN, 128, 128, 2,
                                    b_mix, nullptr, nullptr, nullptr, h);
    }
}

// round 4
// speedup vs baseline: 1.7985x; 1.7985x over previous
#include <cuda_runtime.h>
#include <cuda_bf16.h>
#include <math.h>
#include <stdint.h>

#define NN 50000
#define NE 600000
#define EPS_V 1e-5f
#define AVG_D_LOG 1.6094379124341003f

typedef unsigned long long u64;

// ---------------- scratch ----------------
__device__ float g_PQ[(size_t)NN * 256];            // [P | Q+b_pre]
__device__ __nv_bfloat16 g_aggH[(size_t)NN * 512];  // bf16 hi of agg
__device__ __nv_bfloat16 g_aggL[(size_t)NN * 512];  // bf16 lo residual
__device__ float g_G[(size_t)NN * 384];             // agg @ Wcat (fp32 result)
__device__ float g_hp[(size_t)NN * 128];
__device__ float g_s1[NN];
__device__ float g_s2[NN];
__device__ int   g_count[NN];
__device__ int   g_offsets[NN + 1];
__device__ int   g_cursor[NN];
__device__ int   g_sorted_src[NE];
__device__ float g_B1[128 * 256];
__device__ float g_bias1[256];
__device__ __nv_bfloat16 g_WcatTh[384 * 512];       // transposed, bf16 hi
__device__ __nv_bfloat16 g_WcatTl[384 * 512];       // transposed, bf16 lo
__device__ int   g_blocksums[64];
__device__ int   g_blockoff[64];
__device__ int   g_is64;

// ---------------- index dtype detection ----------------
__global__ void detect_kernel(const void* edst) {
    const int* v = (const int*)edst;
    g_is64 = (v[1] == 0 && v[3] == 0) ? 1 : 0;
}
__device__ __forceinline__ int edge_index(const void* p, int i) {
    if (g_is64) return (int)(((const long long*)p)[i]);
    return ((const int*)p)[i];
}

// ---------------- prep ----------------
__global__ void prep_kernel(const float* __restrict__ W_pre,
                            const float* __restrict__ b_pre,
                            const float* __restrict__ W_post) {
    int idx = blockIdx.x * blockDim.x + threadIdx.x;
    if (idx < NN) g_count[idx] = 0;
    if (idx < 256) g_bias1[idx] = (idx < 128) ? 0.f : b_pre[idx - 128];
    if (idx < 128 * 256) {
        int k = idx >> 8;
        int c = idx & 255;
        g_B1[idx] = (c < 128) ? W_pre[k * 128 + c] : W_pre[(128 + k) * 128 + (c - 128)];
    }
    if (idx < 384 * 512) {
        // WcatT[n][k] = W_post[(128 + grp*512 + k)*128 + jj], n = grp*128+jj
        int n = idx >> 9;
        int k = idx & 511;
        int grp = n >> 7;
        int jj = n & 127;
        float v = W_post[(size_t)(128 + grp * 512 + k) * 128 + jj];
        __nv_bfloat16 hi = __float2bfloat16(v);
        __nv_bfloat16 lo = __float2bfloat16(v - __bfloat162float(hi));
        g_WcatTh[idx] = hi;
        g_WcatTl[idx] = lo;
    }
}

// ---------------- histogram ----------------
__global__ void hist_kernel(const void* __restrict__ edst) {
    int e = blockIdx.x * blockDim.x + threadIdx.x;
    if (e < NE) atomicAdd(&g_count[edge_index(edst, e)], 1);
}

// ---------------- parallel scan ----------------
#define SCAN_BLOCKS ((NN + 1023) / 1024)

__global__ void __launch_bounds__(1024) scanA_kernel() {
    __shared__ int sdata[1024];
    int tid = threadIdx.x;
    int i = blockIdx.x * 1024 + tid;
    int v = (i < NN) ? g_count[i] : 0;
    sdata[tid] = v;
    __syncthreads();
    #pragma unroll
    for (int off = 1; off < 1024; off <<= 1) {
        int t = (tid >= off) ? sdata[tid - off] : 0;
        __syncthreads();
        sdata[tid] += t;
        __syncthreads();
    }
    if (i < NN) g_offsets[i] = sdata[tid] - v;
    if (tid == 1023) g_blocksums[blockIdx.x] = sdata[1023];
}
__global__ void scanB_kernel() {
    if (threadIdx.x == 0) {
        int run = 0;
        for (int b = 0; b < SCAN_BLOCKS; b++) { g_blockoff[b] = run; run += g_blocksums[b]; }
    }
}
__global__ void __launch_bounds__(1024) scanC_kernel() {
    int i = blockIdx.x * 1024 + threadIdx.x;
    if (i < NN) {
        int o = g_offsets[i] + g_blockoff[blockIdx.x];
        g_offsets[i] = o;
        g_cursor[i] = o;
    }
    if (i == 0) g_offsets[NN] = NE;
}

// ---------------- scatter ----------------
__global__ void scatter_kernel(const void* __restrict__ esrc, const void* __restrict__ edst) {
    int e = blockIdx.x * blockDim.x + threadIdx.x;
    if (e < NE) {
        int d = edge_index(edst, e);
        int s = edge_index(esrc, e);
        g_sorted_src[atomicAdd(&g_cursor[d], 1)] = s;
    }
}

// ---------------- scalar SGEMM (round-1, known-good) ----------------
// mode 0: C = acc (+bias) ; mode 1: relu(acc+bias+G0+s1*G1+s2*G2) ; mode 2: resid + leaky(acc+bias)
__global__ void __launch_bounds__(256) sgemm_kernel(
    const float* __restrict__ A, const float* __restrict__ B, float* __restrict__ C,
    int M, int N, int K, int mode,
    const float* __restrict__ bias, const float* __restrict__ Gx,
    const float* __restrict__ s1p, const float* __restrict__ s2p,
    const float* __restrict__ resid)
{
    __shared__ float As[16][128];
    __shared__ float Bs[16][128];
    int tid = threadIdx.x;
    int blockRow = blockIdx.x * 128;
    int blockCol = blockIdx.y * 128;
    int tr = (tid / 16) * 8;
    int tc = (tid % 16) * 8;

    float acc[8][8];
    #pragma unroll
    for (int i = 0; i < 8; i++)
        #pragma unroll
        for (int j = 0; j < 8; j++) acc[i][j] = 0.f;

    int aRow0 = tid >> 2, aCol = (tid & 3) * 4;
    int bRow0 = tid >> 5, bCol = (tid & 31) * 4;

    for (int k0 = 0; k0 < K; k0 += 16) {
        #pragma unroll
        for (int half = 0; half < 2; half++) {
            int r = aRow0 + half * 64;
            int gr = blockRow + r;
            if (gr > M - 1) gr = M - 1;
            float4 v = *reinterpret_cast<const float4*>(&A[(size_t)gr * K + k0 + aCol]);
            As[aCol + 0][r] = v.x; As[aCol + 1][r] = v.y;
            As[aCol + 2][r] = v.z; As[aCol + 3][r] = v.w;
        }
        #pragma unroll
        for (int half = 0; half < 2; half++) {
            int r = bRow0 + half * 8;
            float4 v = *reinterpret_cast<const float4*>(&B[(size_t)(k0 + r) * N + blockCol + bCol]);
            *reinterpret_cast<float4*>(&Bs[r][bCol]) = v;
        }
        __syncthreads();
        #pragma unroll
        for (int k = 0; k < 16; k++) {
            float4 a0 = *reinterpret_cast<float4*>(&As[k][tr]);
            float4 a1 = *reinterpret_cast<float4*>(&As[k][tr + 4]);
            float4 b0 = *reinterpret_cast<float4*>(&Bs[k][tc]);
            float4 b1 = *reinterpret_cast<float4*>(&Bs[k][tc + 4]);
            float ra[8] = {a0.x, a0.y, a0.z, a0.w, a1.x, a1.y, a1.z, a1.w};
            float rb[8] = {b0.x, b0.y, b0.z, b0.w, b1.x, b1.y, b1.z, b1.w};
            #pragma unroll
            for (int i = 0; i < 8; i++)
                #pragma unroll
                for (int j = 0; j < 8; j++)
                    acc[i][j] = fmaf(ra[i], rb[j], acc[i][j]);
        }
        __syncthreads();
    }

    #pragma unroll
    for (int i = 0; i < 8; i++) {
        int row = blockRow + tr + i;
        if (row >= M) break;
        float s1v = 0.f, s2v = 0.f;
        if (mode == 1) { s1v = s1p[row]; s2v = s2p[row]; }
        #pragma unroll
        for (int j = 0; j < 8; j++) {
            int col = blockCol + tc + j;
            float v = acc[i][j];
            if (bias) v += bias[col];
            if (mode == 1) {
                const float* g = &Gx[(size_t)row * 384];
                v += g[col] + s1v * g[col + 128] + s2v * g[col + 256];
                v = fmaxf(v, 0.f);
            } else if (mode == 2) {
                v = (v > 0.f) ? v : 0.01f * v;
                v += resid[(size_t)row * 128 + col];
            }
            C[(size_t)row * N + col] = v;
        }
    }
}

// ---------------- aggregate (writes bf16 hi/lo split) ----------------
__global__ void __launch_bounds__(128) aggregate_kernel() {
    int n = blockIdx.x;
    int d = threadIdx.x;
    int start = g_offsets[n];
    int end = g_offsets[n + 1];
    float qd = g_PQ[(size_t)n * 256 + 128 + d];
    float s = 0.f, sq = 0.f, mx = -3.4e38f, mn = 3.4e38f;
    for (int i = start; i < end; i++) {
        int src = g_sorted_src[i];
        float v = g_PQ[(size_t)src * 256 + d] + qd;
        v = fmaxf(v, 0.f);
        s += v; sq += v * v;
        mx = fmaxf(mx, v); mn = fminf(mn, v);
    }
    float degf = (float)(end - start);
    float inv = 1.f / degf;
    float mean = s * inv;
    float var = fmaxf(sq * inv - mean * mean, 0.f);
    float sd = sqrtf(var + EPS_V);
    size_t base = (size_t)n * 512;
    float vals[4] = {mean, mx, mn, sd};
    #pragma unroll
    for (int t = 0; t < 4; t++) {
        float v = vals[t];
        __nv_bfloat16 hi = __float2bfloat16(v);
        __nv_bfloat16 lo = __float2bfloat16(v - __bfloat162float(hi));
        g_aggH[base + t * 128 + d] = hi;
        g_aggL[base + t * 128 + d] = lo;
    }
    if (d == 0) {
        float ld = logf(degf + 1.f);
        g_s1[n] = ld / AVG_D_LOG;
        g_s2[n] = AVG_D_LOG / ld;
    }
}

// ---------------- GEMM2: mma.sync bf16-split, G[M,384] = agg[M,512] @ Wcat ----------------
// block 256 thr = 8 warps, tile 128(M) x 128(N), warp tile 64x32, K chunks of 64.
// D = AhBh + AhBl + AlBh accumulated into one fp32 acc.

#define MMA16816(c, a, b) \
    asm volatile("mma.sync.aligned.m16n8k16.row.col.f32.bf16.bf16.f32 " \
        "{%0,%1,%2,%3}, {%4,%5,%6,%7}, {%8,%9}, {%0,%1,%2,%3};" \
        : "+f"((c)[0]), "+f"((c)[1]), "+f"((c)[2]), "+f"((c)[3]) \
        : "r"((a)[0]), "r"((a)[1]), "r"((a)[2]), "r"((a)[3]), \
          "r"((b)[0]), "r"((b)[1]))

#define G2_S 72                                    // smem stride in bf16 (36 words: LDS conflict-free)
#define G2_SMEM_BYTES (4 * 128 * G2_S * 2)         // AsH, AsL, BsH, BsL = 73728 B

__global__ void __launch_bounds__(256) tgemm2_kernel(float* __restrict__ C) {
    extern __shared__ __nv_bfloat16 sm[];
    __nv_bfloat16* AsH = sm;
    __nv_bfloat16* AsL = AsH + 128 * G2_S;
    __nv_bfloat16* BsH = AsL + 128 * G2_S;
    __nv_bfloat16* BsL = BsH + 128 * G2_S;

    int tid = threadIdx.x, lane = tid & 31, wid = tid >> 5;
    int warp_m = wid >> 2;          // 0..1 -> 64 rows
    int warp_n = wid & 3;           // 0..3 -> 32 cols
    int blockRow = blockIdx.x * 128, blockCol = blockIdx.y * 128;

    float acc[4][4][4];
    #pragma unroll
    for (int i = 0; i < 4; i++)
        #pragma unroll
        for (int j = 0; j < 4; j++)
            #pragma unroll
            for (int q = 0; q < 4; q++) acc[i][j][q] = 0.f;

    // global loaders: thread t handles row t>>1, 32-elem half t&1
    int ldRow = tid >> 1, ldHalf = tid & 1;
    int aRow = blockRow + ldRow; if (aRow > NN - 1) aRow = NN - 1;
    const uint4* gAH = (const uint4*)(g_aggH + (size_t)aRow * 512 + ldHalf * 32);
    const uint4* gAL = (const uint4*)(g_aggL + (size_t)aRow * 512 + ldHalf * 32);
    const uint4* gBH = (const uint4*)(g_WcatTh + (size_t)(blockCol + ldRow) * 512 + ldHalf * 32);
    const uint4* gBL = (const uint4*)(g_WcatTl + (size_t)(blockCol + ldRow) * 512 + ldHalf * 32);
    uint4* sAH = (uint4*)(AsH + ldRow * G2_S + ldHalf * 32);
    uint4* sAL = (uint4*)(AsL + ldRow * G2_S + ldHalf * 32);
    uint4* sBH = (uint4*)(BsH + ldRow * G2_S + ldHalf * 32);
    uint4* sBL = (uint4*)(BsL + ldRow * G2_S + ldHalf * 32);

    int fr = lane >> 2;             // fragment row 0..7
    int fk = (lane & 3) * 2;        // fragment k-pair

    for (int ch = 0; ch < 8; ch++) {
        #pragma unroll
        for (int j = 0; j < 4; j++) {
            sAH[j] = gAH[ch * 8 + j];
            sAL[j] = gAL[ch * 8 + j];
            sBH[j] = gBH[ch * 8 + j];
            sBL[j] = gBL[ch * 8 + j];
        }
        __syncthreads();
        #pragma unroll
        for (int ks = 0; ks < 4; ks++) {
            int k0 = ks * 16;
            uint32_t bh[4][2], bl[4][2];
            #pragma unroll
            for (int nt = 0; nt < 4; nt++) {
                int nrow = warp_n * 32 + nt * 8 + fr;
                bh[nt][0] = *(const uint32_t*)&BsH[nrow * G2_S + k0 + fk];
                bh[nt][1] = *(const uint32_t*)&BsH[nrow * G2_S + k0 + 8 + fk];
                bl[nt][0] = *(const uint32_t*)&BsL[nrow * G2_S + k0 + fk];
                bl[nt][1] = *(const uint32_t*)&BsL[nrow * G2_S + k0 + 8 + fk];
            }
            #pragma unroll
            for (int mt = 0; mt < 4; mt++) {
                int r0 = warp_m * 64 + mt * 16 + fr;
                uint32_t ah[4], al[4];
                ah[0] = *(const uint32_t*)&AsH[r0 * G2_S + k0 + fk];
                ah[1] = *(const uint32_t*)&AsH[(r0 + 8) * G2_S + k0 + fk];
                ah[2] = *(const uint32_t*)&AsH[r0 * G2_S + k0 + 8 + fk];
                ah[3] = *(const uint32_t*)&AsH[(r0 + 8) * G2_S + k0 + 8 + fk];
                al[0] = *(const uint32_t*)&AsL[r0 * G2_S + k0 + fk];
                al[1] = *(const uint32_t*)&AsL[(r0 + 8) * G2_S + k0 + fk];
                al[2] = *(const uint32_t*)&AsL[r0 * G2_S + k0 + 8 + fk];
                al[3] = *(const uint32_t*)&AsL[(r0 + 8) * G2_S + k0 + 8 + fk];
                #pragma unroll
                for (int nt = 0; nt < 4; nt++) {
                    MMA16816(acc[mt][nt], ah, bh[nt]);
                    MMA16816(acc[mt][nt], ah, bl[nt]);
                    MMA16816(acc[mt][nt], al, bh[nt]);
                }
            }
        }
        __syncthreads();
    }

    // epilogue: c0,c1 -> (row, col..col+1); c2,c3 -> (row+8, ...)
    #pragma unroll
    for (int mt = 0; mt < 4; mt++) {
        int row = blockRow + warp_m * 64 + mt * 16 + fr;
        #pragma unroll
        for (int nt = 0; nt < 4; nt++) {
            int col = blockCol + warp_n * 32 + nt * 8 + ((lane & 3) * 2);
            if (row < NN)
                *(float2*)&C[(size_t)row * 384 + col] = make_float2(acc[mt][nt][0], acc[mt][nt][1]);
            if (row + 8 < NN)
                *(float2*)&C[(size_t)(row + 8) * 384 + col] = make_float2(acc[mt][nt][2], acc[mt][nt][3]);
        }
    }
}

// ---------------- launch ----------------
extern "C" void kernel_launch(void* const* d_in, const int* in_sizes, int n_in,
                              void* d_out, int out_size) {
    const float* h      = (const float*)d_in[0];
    const void*  esrc   = d_in[1];
    const void*  edst   = d_in[2];
    const float* W_pre  = (const float*)d_in[3];
    const float* b_pre  = (const float*)d_in[4];
    const float* W_post = (const float*)d_in[5];
    const float* b_post = (const float*)d_in[6];
    const float* W_mix  = (const float*)d_in[7];
    const float* b_mix  = (const float*)d_in[8];
    float* out = (float*)d_out;

    float *g_PQ_p, *g_G_p, *g_hp_p, *g_s1_p, *g_s2_p, *g_B1_p, *g_bias1_p;
    cudaGetSymbolAddress((void**)&g_PQ_p, g_PQ);
    cudaGetSymbolAddress((void**)&g_G_p, g_G);
    cudaGetSymbolAddress((void**)&g_hp_p, g_hp);
    cudaGetSymbolAddress((void**)&g_s1_p, g_s1);
    cudaGetSymbolAddress((void**)&g_s2_p, g_s2);
    cudaGetSymbolAddress((void**)&g_B1_p, g_B1);
    cudaGetSymbolAddress((void**)&g_bias1_p, g_bias1);

    static int smem_set = 0;
    if (!smem_set) {
        cudaFuncSetAttribute(tgemm2_kernel, cudaFuncAttributeMaxDynamicSharedMemorySize, G2_SMEM_BYTES);
        smem_set = 1;
    }

    detect_kernel<<<1, 1>>>(edst);
    prep_kernel<<<768, 256>>>(W_pre, b_pre, W_post);
    hist_kernel<<<(NE + 255) / 256, 256>>>(edst);
    scanA_kernel<<<SCAN_BLOCKS, 1024>>>();
    scanB_kernel<<<1, 32>>>();
    scanC_kernel<<<SCAN_BLOCKS, 1024>>>();
    scatter_kernel<<<(NE + 255) / 256, 256>>>(esrc, edst);

    // GEMM1: PQ = h @ B1 (+bias1)
    {
        dim3 grid((NN + 127) / 128, 2);
        sgemm_kernel<<<grid, 256>>>(h, g_B1_p, g_PQ_p, NN, 256, 128, 0,
                                    g_bias1_p, nullptr, nullptr, nullptr, nullptr);
    }

    aggregate_kernel<<<NN, 128>>>();

    // GEMM2 (tensor, bf16-split): G = agg @ Wcat
    {
        dim3 grid((NN + 127) / 128, 3);
        tgemm2_kernel<<<grid, 256, G2_SMEM_BYTES>>>(g_G_p);
    }

    // GEMM3: hp = relu(h @ W_post[0:128] + comb(G,s1,s2) + b_post)
    {
        dim3 grid((NN + 127) / 128, 1);
        sgemm_kernel<<<grid, 256>>>(h, W_post, g_hp_p, NN, 128, 128, 1,
                                    b_post, g_G_p, g_s1_p, g_s2_p, nullptr);
    }

    // GEMM4: out = h + leaky_relu(hp @ W_mix + b_mix)
    {
        dim3 grid((NN + 127) / 128, 1);
        sgemm_kernel<<<grid, 256>>>(g_hp_p, W_mix, out, NN, 128, 128, 2,
                                    b_mix, nullptr, nullptr, nullptr, h);
    }
}

// round 5
// speedup vs baseline: 2.1926x; 1.2191x over previous
#include <cuda_runtime.h>
#include <cuda_bf16.h>
#include <math.h>
#include <stdint.h>

#define NN 50000
#define NE 600000
#define EPS_V 1e-5f
#define AVG_D_LOG 1.6094379124341003f

typedef unsigned long long u64;

// ---------------- scratch ----------------
__device__ float g_PQ[(size_t)NN * 256];            // [P | Q+b_pre]
__device__ __nv_bfloat16 g_hH[(size_t)NN * 128];    // h split hi
__device__ __nv_bfloat16 g_hL[(size_t)NN * 128];    // h split lo
__device__ __nv_bfloat16 g_aggH[(size_t)NN * 512];
__device__ __nv_bfloat16 g_aggL[(size_t)NN * 512];
__device__ __nv_bfloat16 g_hpH[(size_t)NN * 128];   // hp split hi
__device__ __nv_bfloat16 g_hpL[(size_t)NN * 128];   // hp split lo
__device__ float g_G[(size_t)NN * 384];             // agg @ Wcat
__device__ float g_s1[NN];
__device__ float g_s2[NN];
__device__ int   g_count[NN];
__device__ int   g_offsets[NN + 1];
__device__ int   g_cursor[NN];
__device__ int   g_sorted_src[NE];
__device__ float g_bias1[256];
__device__ __nv_bfloat16 g_B1Th[256 * 128];         // B1^T split (GEMM1 B)
__device__ __nv_bfloat16 g_B1Tl[256 * 128];
__device__ __nv_bfloat16 g_Wp0Th[128 * 128];        // W_post[0:128]^T split (GEMM3 B)
__device__ __nv_bfloat16 g_Wp0Tl[128 * 128];
__device__ __nv_bfloat16 g_WmixTh[128 * 128];       // W_mix^T split (GEMM4 B)
__device__ __nv_bfloat16 g_WmixTl[128 * 128];
__device__ __nv_bfloat16 g_WcatTh[384 * 512];       // Wcat^T split (GEMM2 B)
__device__ __nv_bfloat16 g_WcatTl[384 * 512];
__device__ int   g_blocksums[64];
__device__ int   g_blockoff[64];
__device__ int   g_is64;

// ---------------- index dtype detection ----------------
__global__ void detect_kernel(const void* edst) {
    const int* v = (const int*)edst;
    g_is64 = (v[1] == 0 && v[3] == 0) ? 1 : 0;
}
__device__ __forceinline__ int edge_index(const void* p, int i) {
    if (g_is64) return (int)(((const long long*)p)[i]);
    return ((const int*)p)[i];
}

__device__ __forceinline__ void split2(float v, __nv_bfloat16* hi, __nv_bfloat16* lo) {
    __nv_bfloat16 h = __float2bfloat16(v);
    *hi = h;
    *lo = __float2bfloat16(v - __bfloat162float(h));
}

// ---------------- prep: counters, bias1, split weights ----------------
__global__ void prep_kernel(const float* __restrict__ W_pre,
                            const float* __restrict__ b_pre,
                            const float* __restrict__ W_post,
                            const float* __restrict__ W_mix) {
    int idx = blockIdx.x * blockDim.x + threadIdx.x;
    if (idx < NN) g_count[idx] = 0;
    if (idx < 256) g_bias1[idx] = (idx < 128) ? 0.f : b_pre[idx - 128];
    if (idx < 256 * 128) {
        // B1T[n][k]: n<128 -> W_pre[k*128+n] ; n>=128 -> W_pre[(128+k)*128 + (n-128)]
        int n = idx >> 7, k = idx & 127;
        float v = (n < 128) ? W_pre[k * 128 + n] : W_pre[(128 + k) * 128 + (n - 128)];
        split2(v, &g_B1Th[idx], &g_B1Tl[idx]);
    }
    if (idx < 128 * 128) {
        int n = idx >> 7, k = idx & 127;
        split2(W_post[k * 128 + n], &g_Wp0Th[idx], &g_Wp0Tl[idx]);
        split2(W_mix[k * 128 + n], &g_WmixTh[idx], &g_WmixTl[idx]);
    }
    if (idx < 384 * 512) {
        int n = idx >> 9, k = idx & 511;
        int grp = n >> 7, jj = n & 127;
        split2(W_post[(size_t)(128 + grp * 512 + k) * 128 + jj], &g_WcatTh[idx], &g_WcatTl[idx]);
    }
}

// ---------------- split h -> bf16 hi/lo ----------------
__global__ void __launch_bounds__(256) split_h_kernel(const float* __restrict__ h) {
    int i = blockIdx.x * blockDim.x + threadIdx.x;
    int idx = i * 4;
    if (idx < NN * 128) {
        float4 v = *(const float4*)(h + idx);
        float vv[4] = {v.x, v.y, v.z, v.w};
        #pragma unroll
        for (int j = 0; j < 4; j++)
            split2(vv[j], &g_hH[idx + j], &g_hL[idx + j]);
    }
}

// ---------------- histogram ----------------
__global__ void hist_kernel(const void* __restrict__ edst) {
    int e = blockIdx.x * blockDim.x + threadIdx.x;
    if (e < NE) atomicAdd(&g_count[edge_index(edst, e)], 1);
}

// ---------------- parallel scan ----------------
#define SCAN_BLOCKS ((NN + 1023) / 1024)

__global__ void __launch_bounds__(1024) scanA_kernel() {
    __shared__ int sdata[1024];
    int tid = threadIdx.x;
    int i = blockIdx.x * 1024 + tid;
    int v = (i < NN) ? g_count[i] : 0;
    sdata[tid] = v;
    __syncthreads();
    #pragma unroll
    for (int off = 1; off < 1024; off <<= 1) {
        int t = (tid >= off) ? sdata[tid - off] : 0;
        __syncthreads();
        sdata[tid] += t;
        __syncthreads();
    }
    if (i < NN) g_offsets[i] = sdata[tid] - v;
    if (tid == 1023) g_blocksums[blockIdx.x] = sdata[1023];
}
__global__ void scanB_kernel() {
    if (threadIdx.x == 0) {
        int run = 0;
        for (int b = 0; b < SCAN_BLOCKS; b++) { g_blockoff[b] = run; run += g_blocksums[b]; }
    }
}
__global__ void __launch_bounds__(1024) scanC_kernel() {
    int i = blockIdx.x * 1024 + threadIdx.x;
    if (i < NN) {
        int o = g_offsets[i] + g_blockoff[blockIdx.x];
        g_offsets[i] = o;
        g_cursor[i] = o;
    }
    if (i == 0) g_offsets[NN] = NE;
}

// ---------------- scatter ----------------
__global__ void scatter_kernel(const void* __restrict__ esrc, const void* __restrict__ edst) {
    int e = blockIdx.x * blockDim.x + threadIdx.x;
    if (e < NE) {
        int d = edge_index(edst, e);
        int s = edge_index(esrc, e);
        g_sorted_src[atomicAdd(&g_cursor[d], 1)] = s;
    }
}

// ---------------- aggregate (reads fp32 PQ, writes bf16 split agg) ----------------
__global__ void __launch_bounds__(128) aggregate_kernel() {
    int n = blockIdx.x;
    int d = threadIdx.x;
    int start = g_offsets[n];
    int end = g_offsets[n + 1];
    float qd = g_PQ[(size_t)n * 256 + 128 + d];
    float s = 0.f, sq = 0.f, mx = -3.4e38f, mn = 3.4e38f;
    for (int i = start; i < end; i++) {
        int src = g_sorted_src[i];
        float v = g_PQ[(size_t)src * 256 + d] + qd;
        v = fmaxf(v, 0.f);
        s += v; sq += v * v;
        mx = fmaxf(mx, v); mn = fminf(mn, v);
    }
    float degf = (float)(end - start);
    float inv = 1.f / degf;
    float mean = s * inv;
    float var = fmaxf(sq * inv - mean * mean, 0.f);
    float sd = sqrtf(var + EPS_V);
    size_t base = (size_t)n * 512;
    float vals[4] = {mean, mx, mn, sd};
    #pragma unroll
    for (int t = 0; t < 4; t++)
        split2(vals[t], &g_aggH[base + t * 128 + d], &g_aggL[base + t * 128 + d]);
    if (d == 0) {
        float ld = logf(degf + 1.f);
        g_s1[n] = ld / AVG_D_LOG;
        g_s2[n] = AVG_D_LOG / ld;
    }
}

// ---------------- unified bf16-split mma.sync GEMM ----------------
// tile 128x128, 8 warps (warp tile 64x32), K in chunks of 64.
// D = AhBh + AhBl + AlBh into fp32 acc.
// mode 0: C[row*N+col] = acc (+bias)
// mode 1: v = relu(acc + bias + G0 + s1*G1 + s2*G2); write split bf16 to outH/outL (N=128)
// mode 2: C = resid + leaky_relu(acc + bias)  (N=128)

#define MMA16816(c, a, b) \
    asm volatile("mma.sync.aligned.m16n8k16.row.col.f32.bf16.bf16.f32 " \
        "{%0,%1,%2,%3}, {%4,%5,%6,%7}, {%8,%9}, {%0,%1,%2,%3};" \
        : "+f"((c)[0]), "+f"((c)[1]), "+f"((c)[2]), "+f"((c)[3]) \
        : "r"((a)[0]), "r"((a)[1]), "r"((a)[2]), "r"((a)[3]), \
          "r"((b)[0]), "r"((b)[1]))

#define G2_S 72
#define G2_SMEM_BYTES (4 * 128 * G2_S * 2)

__global__ void __launch_bounds__(256) tgemm_kernel(
    const __nv_bfloat16* __restrict__ aHp, const __nv_bfloat16* __restrict__ aLp,
    const __nv_bfloat16* __restrict__ bHp, const __nv_bfloat16* __restrict__ bLp,
    float* __restrict__ C, int M, int N, int K, int mode,
    const float* __restrict__ bias, const float* __restrict__ Gx,
    const float* __restrict__ s1p, const float* __restrict__ s2p,
    const float* __restrict__ resid,
    __nv_bfloat16* __restrict__ outH, __nv_bfloat16* __restrict__ outL)
{
    extern __shared__ __nv_bfloat16 sm[];
    __nv_bfloat16* AsH = sm;
    __nv_bfloat16* AsL = AsH + 128 * G2_S;
    __nv_bfloat16* BsH = AsL + 128 * G2_S;
    __nv_bfloat16* BsL = BsH + 128 * G2_S;

    int tid = threadIdx.x, lane = tid & 31, wid = tid >> 5;
    int warp_m = wid >> 2;
    int warp_n = wid & 3;
    int blockRow = blockIdx.x * 128, blockCol = blockIdx.y * 128;

    float acc[4][4][4];
    #pragma unroll
    for (int i = 0; i < 4; i++)
        #pragma unroll
        for (int j = 0; j < 4; j++)
            #pragma unroll
            for (int q = 0; q < 4; q++) acc[i][j][q] = 0.f;

    int ldRow = tid >> 1, ldHalf = tid & 1;
    int aRow = blockRow + ldRow; if (aRow > M - 1) aRow = M - 1;
    const uint4* gAH = (const uint4*)(aHp + (size_t)aRow * K + ldHalf * 32);
    const uint4* gAL = (const uint4*)(aLp + (size_t)aRow * K + ldHalf * 32);
    const uint4* gBH = (const uint4*)(bHp + (size_t)(blockCol + ldRow) * K + ldHalf * 32);
    const uint4* gBL = (const uint4*)(bLp + (size_t)(blockCol + ldRow) * K + ldHalf * 32);
    uint4* sAH = (uint4*)(AsH + ldRow * G2_S + ldHalf * 32);
    uint4* sAL = (uint4*)(AsL + ldRow * G2_S + ldHalf * 32);
    uint4* sBH = (uint4*)(BsH + ldRow * G2_S + ldHalf * 32);
    uint4* sBL = (uint4*)(BsL + ldRow * G2_S + ldHalf * 32);

    int fr = lane >> 2;
    int fk = (lane & 3) * 2;
    int nch = K >> 6;

    for (int ch = 0; ch < nch; ch++) {
        #pragma unroll
        for (int j = 0; j < 4; j++) {
            sAH[j] = gAH[ch * 8 + j];
            sAL[j] = gAL[ch * 8 + j];
            sBH[j] = gBH[ch * 8 + j];
            sBL[j] = gBL[ch * 8 + j];
        }
        __syncthreads();
        #pragma unroll
        for (int ks = 0; ks < 4; ks++) {
            int k0 = ks * 16;
            uint32_t bh[4][2], bl[4][2];
            #pragma unroll
            for (int nt = 0; nt < 4; nt++) {
                int nrow = warp_n * 32 + nt * 8 + fr;
                bh[nt][0] = *(const uint32_t*)&BsH[nrow * G2_S + k0 + fk];
                bh[nt][1] = *(const uint32_t*)&BsH[nrow * G2_S + k0 + 8 + fk];
                bl[nt][0] = *(const uint32_t*)&BsL[nrow * G2_S + k0 + fk];
                bl[nt][1] = *(const uint32_t*)&BsL[nrow * G2_S + k0 + 8 + fk];
            }
            #pragma unroll
            for (int mt = 0; mt < 4; mt++) {
                int r0 = warp_m * 64 + mt * 16 + fr;
                uint32_t ah[4], al[4];
                ah[0] = *(const uint32_t*)&AsH[r0 * G2_S + k0 + fk];
                ah[1] = *(const uint32_t*)&AsH[(r0 + 8) * G2_S + k0 + fk];
                ah[2] = *(const uint32_t*)&AsH[r0 * G2_S + k0 + 8 + fk];
                ah[3] = *(const uint32_t*)&AsH[(r0 + 8) * G2_S + k0 + 8 + fk];
                al[0] = *(const uint32_t*)&AsL[r0 * G2_S + k0 + fk];
                al[1] = *(const uint32_t*)&AsL[(r0 + 8) * G2_S + k0 + fk];
                al[2] = *(const uint32_t*)&AsL[r0 * G2_S + k0 + 8 + fk];
                al[3] = *(const uint32_t*)&AsL[(r0 + 8) * G2_S + k0 + 8 + fk];
                #pragma unroll
                for (int nt = 0; nt < 4; nt++) {
                    MMA16816(acc[mt][nt], ah, bh[nt]);
                    MMA16816(acc[mt][nt], ah, bl[nt]);
                    MMA16816(acc[mt][nt], al, bh[nt]);
                }
            }
        }
        __syncthreads();
    }

    // epilogue
    #pragma unroll
    for (int mt = 0; mt < 4; mt++) {
        int row0 = blockRow + warp_m * 64 + mt * 16 + fr;
        #pragma unroll
        for (int half = 0; half < 2; half++) {
            int row = row0 + half * 8;
            if (row >= M) continue;
            #pragma unroll
            for (int nt = 0; nt < 4; nt++) {
                int col = blockCol + warp_n * 32 + nt * 8 + ((lane & 3) * 2);
                float v0 = acc[mt][nt][half * 2];
                float v1 = acc[mt][nt][half * 2 + 1];
                if (bias) { v0 += bias[col]; v1 += bias[col + 1]; }
                if (mode == 0) {
                    *(float2*)&C[(size_t)row * N + col] = make_float2(v0, v1);
                } else if (mode == 1) {
                    float s1v = s1p[row], s2v = s2p[row];
                    const float* g = &Gx[(size_t)row * 384];
                    v0 += g[col] + s1v * g[col + 128] + s2v * g[col + 256];
                    v1 += g[col + 1] + s1v * g[col + 129] + s2v * g[col + 257];
                    v0 = fmaxf(v0, 0.f);
                    v1 = fmaxf(v1, 0.f);
                    size_t o = (size_t)row * 128 + col;
                    split2(v0, &outH[o], &outL[o]);
                    split2(v1, &outH[o + 1], &outL[o + 1]);
                } else {
                    v0 = (v0 > 0.f) ? v0 : 0.01f * v0;
                    v1 = (v1 > 0.f) ? v1 : 0.01f * v1;
                    size_t o = (size_t)row * 128 + col;
                    v0 += resid[o];
                    v1 += resid[o + 1];
                    *(float2*)&C[o] = make_float2(v0, v1);
                }
            }
        }
    }
}

// ---------------- launch ----------------
extern "C" void kernel_launch(void* const* d_in, const int* in_sizes, int n_in,
                              void* d_out, int out_size) {
    const float* h      = (const float*)d_in[0];
    const void*  esrc   = d_in[1];
    const void*  edst   = d_in[2];
    const float* W_pre  = (const float*)d_in[3];
    const float* b_pre  = (const float*)d_in[4];
    const float* W_post = (const float*)d_in[5];
    const float* b_post = (const float*)d_in[6];
    const float* W_mix  = (const float*)d_in[7];
    const float* b_mix  = (const float*)d_in[8];
    float* out = (float*)d_out;

    float *PQ, *G, *s1, *s2, *bias1;
    __nv_bfloat16 *hH, *hL, *aggH, *aggL, *hpH, *hpL;
    __nv_bfloat16 *B1Th, *B1Tl, *Wp0Th, *Wp0Tl, *WmixTh, *WmixTl, *WcatTh, *WcatTl;
    cudaGetSymbolAddress((void**)&PQ, g_PQ);
    cudaGetSymbolAddress((void**)&G, g_G);
    cudaGetSymbolAddress((void**)&s1, g_s1);
    cudaGetSymbolAddress((void**)&s2, g_s2);
    cudaGetSymbolAddress((void**)&bias1, g_bias1);
    cudaGetSymbolAddress((void**)&hH, g_hH);
    cudaGetSymbolAddress((void**)&hL, g_hL);
    cudaGetSymbolAddress((void**)&aggH, g_aggH);
    cudaGetSymbolAddress((void**)&aggL, g_aggL);
    cudaGetSymbolAddress((void**)&hpH, g_hpH);
    cudaGetSymbolAddress((void**)&hpL, g_hpL);
    cudaGetSymbolAddress((void**)&B1Th, g_B1Th);
    cudaGetSymbolAddress((void**)&B1Tl, g_B1Tl);
    cudaGetSymbolAddress((void**)&Wp0Th, g_Wp0Th);
    cudaGetSymbolAddress((void**)&Wp0Tl, g_Wp0Tl);
    cudaGetSymbolAddress((void**)&WmixTh, g_WmixTh);
    cudaGetSymbolAddress((void**)&WmixTl, g_WmixTl);
    cudaGetSymbolAddress((void**)&WcatTh, g_WcatTh);
    cudaGetSymbolAddress((void**)&WcatTl, g_WcatTl);

    static int smem_set = 0;
    if (!smem_set) {
        cudaFuncSetAttribute(tgemm_kernel, cudaFuncAttributeMaxDynamicSharedMemorySize, G2_SMEM_BYTES);
        smem_set = 1;
    }

    detect_kernel<<<1, 1>>>(edst);
    prep_kernel<<<768, 256>>>(W_pre, b_pre, W_post, W_mix);
    split_h_kernel<<<(NN * 128 / 4 + 255) / 256, 256>>>(h);
    hist_kernel<<<(NE + 255) / 256, 256>>>(edst);
    scanA_kernel<<<SCAN_BLOCKS, 1024>>>();
    scanB_kernel<<<1, 32>>>();
    scanC_kernel<<<SCAN_BLOCKS, 1024>>>();
    scatter_kernel<<<(NE + 255) / 256, 256>>>(esrc, edst);

    const int GB = (NN + 127) / 128;

    // GEMM1: PQ = h @ B1 (+bias1)   N=256, K=128
    tgemm_kernel<<<dim3(GB, 2), 256, G2_SMEM_BYTES>>>(
        hH, hL, B1Th, B1Tl, PQ, NN, 256, 128, 0,
        bias1, nullptr, nullptr, nullptr, nullptr, nullptr, nullptr);

    aggregate_kernel<<<NN, 128>>>();

    // GEMM2: G = agg @ Wcat   N=384, K=512
    tgemm_kernel<<<dim3(GB, 3), 256, G2_SMEM_BYTES>>>(
        aggH, aggL, WcatTh, WcatTl, G, NN, 384, 512, 0,
        nullptr, nullptr, nullptr, nullptr, nullptr, nullptr, nullptr);

    // GEMM3: hp = relu(h @ Wp0 + comb(G,s1,s2) + b_post) -> split bf16
    tgemm_kernel<<<dim3(GB, 1), 256, G2_SMEM_BYTES>>>(
        hH, hL, Wp0Th, Wp0Tl, nullptr, NN, 128, 128, 1,
        b_post, G, s1, s2, nullptr, hpH, hpL);

    // GEMM4: out = h + leaky_relu(hp @ W_mix + b_mix)
    tgemm_kernel<<<dim3(GB, 1), 256, G2_SMEM_BYTES>>>(
        hpH, hpL, WmixTh, WmixTl, out, NN, 128, 128, 2,
        b_mix, nullptr, nullptr, nullptr, h, nullptr, nullptr);
}